// round 10
// baseline (speedup 1.0000x reference)
#include <cuda_runtime.h>
#include <mma.h>

using namespace nvcuda;

#define NVERT 6890
#define NVC 6912            // padded vertex stride
#define NSTR (3 * NVC)      // 20736 columns in blend GEMM
#define NJ 24
#define NB 10
#define NP 207
#define KP 208              // padded K for GEMM
#define MAXB 1024
#define TB 16
#define TBH 8
#define CBLK 128
#define VSPL 8
#define VCH 862
#define BM 64
#define BN 128

typedef unsigned long long u64;

__device__ __forceinline__ u64 pack2(float x) {
    u64 r; asm("mov.b64 %0,{%1,%1};" : "=l"(r) : "f"(x)); return r;
}
__device__ __forceinline__ u64 pack_pair(float a, float b) {
    u64 r; asm("mov.b64 %0,{%1,%2};" : "=l"(r) : "f"(a), "f"(b)); return r;
}
__device__ __forceinline__ void unpack2(u64 v, float& a, float& b) {
    asm("mov.b64 {%0,%1},%2;" : "=f"(a), "=f"(b) : "l"(v));
}
__device__ __forceinline__ u64 fma2(u64 a, u64 b, u64 c) {
    u64 d; asm("fma.rn.f32x2 %0,%1,%2,%3;" : "=l"(d) : "l"(a), "l"(b), "l"(c)); return d;
}
__device__ __forceinline__ u64 add2(u64 a, u64 b) {
    u64 d; asm("add.rn.f32x2 %0,%1,%2;" : "=l"(d) : "l"(a), "l"(b)); return d;
}

__constant__ int c_par[NJ] = {-1, 0, 0, 0, 1, 2, 3, 4, 5, 6, 7, 8, 9, 9, 9,
                              12, 13, 14, 16, 17, 18, 19, 20, 21};

__device__ float g_JrT[NJ * 3];
__device__ float g_JrS[NJ * 3 * NB];
__device__ float g_G[MAXB * NJ * 12];
__device__ float g_lrotP[MAXB * KP];              // A matrix [b][k], zero-padded
__device__ float g_pdG[(size_t)KP * NSTR];        // B matrix [k][c*NVC+v]
__device__ float g_vp[(size_t)MAXB * NSTR];       // C scratch: pose blend result
__device__ float g_sdT[3 * NB * NVERT];           // [c*NB + s][v]
__device__ float g_wT[NJ * NVERT];                // [j][v]
__device__ float g_vtT[3 * NVERT];                // [c][v]

// ---------------------------------------------------------------------------
// kTpdG: pd[v][c][p] -> g_pdG[p][c*NVC+v], zero-padded rows/cols.
// ---------------------------------------------------------------------------
__global__ __launch_bounds__(256) void kTpdG(const float* __restrict__ pd) {
    __shared__ float tile[32][33];
    int c = blockIdx.z;
    int p0 = blockIdx.x * 32, v0 = blockIdx.y * 32;
    for (int r = threadIdx.y; r < 32; r += 8) {
        int v = v0 + r, p = p0 + threadIdx.x;
        tile[r][threadIdx.x] =
            (v < NVERT && p < NP) ? pd[((size_t)v * 3 + c) * NP + p] : 0.f;
    }
    __syncthreads();
    for (int r = threadIdx.y; r < 32; r += 8) {
        int p = p0 + r, v = v0 + threadIdx.x;
        if (p < KP)
            g_pdG[(size_t)p * NSTR + c * NVC + v] = tile[threadIdx.x][r];
    }
}

// ---------------------------------------------------------------------------
// kT3: three small transposes in one launch (z: 0=weights,1=shapedirs,2=vt)
// ---------------------------------------------------------------------------
__global__ __launch_bounds__(256) void kT3(const float* __restrict__ wgt,
                                           const float* __restrict__ sd,
                                           const float* __restrict__ vt) {
    __shared__ float tile[32][33];
    const float* in; float* out; int K;
    if (blockIdx.z == 0)      { in = wgt; out = g_wT;  K = NJ; }
    else if (blockIdx.z == 1) { in = sd;  out = g_sdT; K = 3 * NB; }
    else                      { in = vt;  out = g_vtT; K = 3; }
    int v0 = blockIdx.x * 32;
    for (int r = threadIdx.y; r < 32; r += 8) {
        int v = v0 + r, k = threadIdx.x;
        tile[r][k] = (v < NVERT && k < K) ? in[(size_t)v * K + k] : 0.f;
    }
    __syncthreads();
    for (int r = threadIdx.y; r < 32; r += 8) {
        int k = r, v = v0 + threadIdx.x;
        if (k < K && v < NVERT) out[(size_t)k * NVERT + v] = tile[threadIdx.x][r];
    }
}

// ---------------------------------------------------------------------------
// Kernel A: fold J_regressor into v_template and shapedirs (coalesced).
// ---------------------------------------------------------------------------
__global__ __launch_bounds__(256) void kA(const float* __restrict__ Jr) {
    int j = blockIdx.x;
    float acc[33];
#pragma unroll
    for (int k = 0; k < 33; ++k) acc[k] = 0.f;

    for (int v = threadIdx.x; v < NVERT; v += blockDim.x) {
        float w = Jr[j * NVERT + v];
#pragma unroll
        for (int c = 0; c < 3; ++c)
            acc[c] = fmaf(w, __ldg(&g_vtT[c * NVERT + v]), acc[c]);
#pragma unroll
        for (int k = 0; k < 3 * NB; ++k)
            acc[3 + k] = fmaf(w, __ldg(&g_sdT[(size_t)k * NVERT + v]), acc[3 + k]);
    }
#pragma unroll
    for (int k = 0; k < 33; ++k) {
#pragma unroll
        for (int off = 16; off > 0; off >>= 1)
            acc[k] += __shfl_xor_sync(0xffffffffu, acc[k], off);
    }
    __shared__ float sm[33];
    if (threadIdx.x < 33) sm[threadIdx.x] = 0.f;
    __syncthreads();
    if ((threadIdx.x & 31) == 0) {
#pragma unroll
        for (int k = 0; k < 33; ++k) atomicAdd(&sm[k], acc[k]);
    }
    __syncthreads();
    if (threadIdx.x < 3) g_JrT[j * 3 + threadIdx.x] = sm[threadIdx.x];
    if (threadIdx.x >= 3 && threadIdx.x < 33)
        g_JrS[j * 3 * NB + threadIdx.x - 3] = sm[threadIdx.x];
}

// ---------------------------------------------------------------------------
// Kernel B: per-batch joints, Rodrigues, chain, G, lrotP, zero joints.
// ---------------------------------------------------------------------------
__global__ __launch_bounds__(32) void kB(const float* __restrict__ betas,
                                         const float* __restrict__ thetas,
                                         const float* __restrict__ scale,
                                         float* __restrict__ joints) {
    int b = blockIdx.x;
    int t = threadIdx.x;
    __shared__ float R[NJ][9];
    __shared__ float J[NJ][3];
    __shared__ float W[NJ][12];

    for (int idx = t; idx < NJ * 3; idx += 32)
        joints[(size_t)b * NJ * 3 + idx] = 0.f;

    if (t < NJ) {
#pragma unroll
        for (int c = 0; c < 3; ++c) {
            float s = g_JrT[t * 3 + c];
#pragma unroll
            for (int k = 0; k < NB; ++k)
                s = fmaf(g_JrS[t * 3 * NB + c * NB + k], betas[b * NB + k], s);
            J[t][c] = s;
        }
        float x = thetas[b * NJ * 3 + t * 3 + 0];
        float y = thetas[b * NJ * 3 + t * 3 + 1];
        float z = thetas[b * NJ * 3 + t * 3 + 2];
        float th = sqrtf(x * x + y * y + z * z) + 1e-8f;
        float rx = x / th, ry = y / th, rz = z / th;
        float cth = cosf(th), sth = sinf(th), ic = 1.f - cth;
        float r[9];
        r[0] = cth + ic * rx * rx;
        r[1] = ic * rx * ry - sth * rz;
        r[2] = ic * rx * rz + sth * ry;
        r[3] = ic * rx * ry + sth * rz;
        r[4] = cth + ic * ry * ry;
        r[5] = ic * ry * rz - sth * rx;
        r[6] = ic * rx * rz - sth * ry;
        r[7] = ic * ry * rz + sth * rx;
        r[8] = cth + ic * rz * rz;
        if (t == 0) {
            float sc = scale[0];
#pragma unroll
            for (int k = 0; k < 9; ++k) r[k] *= sc;
        }
#pragma unroll
        for (int k = 0; k < 9; ++k) R[t][k] = r[k];
    }
    __syncthreads();

    if (t == 0) {
#pragma unroll
        for (int rr = 0; rr < 3; ++rr) {
            W[0][rr * 4 + 0] = R[0][rr * 3 + 0];
            W[0][rr * 4 + 1] = R[0][rr * 3 + 1];
            W[0][rr * 4 + 2] = R[0][rr * 3 + 2];
            W[0][rr * 4 + 3] = J[0][rr];
        }
        for (int i = 1; i < NJ; ++i) {
            int p = c_par[i];
            float tx = J[i][0] - J[p][0];
            float ty = J[i][1] - J[p][1];
            float tz = J[i][2] - J[p][2];
#pragma unroll
            for (int rr = 0; rr < 3; ++rr) {
                float w0 = W[p][rr * 4 + 0], w1 = W[p][rr * 4 + 1],
                      w2 = W[p][rr * 4 + 2], w3 = W[p][rr * 4 + 3];
#pragma unroll
                for (int cc = 0; cc < 3; ++cc)
                    W[i][rr * 4 + cc] = w0 * R[i][0 * 3 + cc] +
                                        w1 * R[i][1 * 3 + cc] +
                                        w2 * R[i][2 * 3 + cc];
                W[i][rr * 4 + 3] = w0 * tx + w1 * ty + w2 * tz + w3;
            }
        }
    }
    __syncthreads();

    if (t < NJ) {
        float* g = g_G + ((size_t)b * NJ + t) * 12;
#pragma unroll
        for (int rr = 0; rr < 3; ++rr) {
            float w0 = W[t][rr * 4 + 0], w1 = W[t][rr * 4 + 1],
                  w2 = W[t][rr * 4 + 2], w3 = W[t][rr * 4 + 3];
            g[rr * 4 + 0] = w0;
            g[rr * 4 + 1] = w1;
            g[rr * 4 + 2] = w2;
            g[rr * 4 + 3] = w3 - (w0 * J[t][0] + w1 * J[t][1] + w2 * J[t][2]);
        }
    }
    // lrot row for the GEMM, zero-padded to KP
    for (int idx = t; idx < KP; idx += 32) {
        float v = 0.f;
        if (idx < NP) {
            int j = idx / 9 + 1;
            int rc = idx % 9;
            v = R[j][rc];
            if (rc == 0 || rc == 4 || rc == 8) v -= 1.f;
        }
        g_lrotP[(size_t)b * KP + idx] = v;
    }
}

// ---------------------------------------------------------------------------
// Kernel G: pose blend GEMM on tensor cores (wmma tf32).
// C[b, c*NVC+v] = sum_k lrotP[b,k] * pdG[k, c*NVC+v]
// block = 256 thr (8 warps, 2x4), tile 64x128, warp tile 32x32.
// ---------------------------------------------------------------------------
__global__ __launch_bounds__(256) void kG() {
    int nt = blockIdx.x;
    int mt = blockIdx.y;
    int warp = threadIdx.x >> 5;
    int wm = warp >> 2;          // 0..1
    int wn = warp & 3;           // 0..3
    int m0 = mt * BM + wm * 32;
    int n0 = nt * BN + wn * 32;

    wmma::fragment<wmma::accumulator, 16, 16, 8, float> acc[2][2];
#pragma unroll
    for (int i = 0; i < 2; ++i)
#pragma unroll
        for (int j = 0; j < 2; ++j) wmma::fill_fragment(acc[i][j], 0.f);

    for (int k = 0; k < KP; k += 8) {
        wmma::fragment<wmma::matrix_a, 16, 16, 8, wmma::precision::tf32,
                       wmma::row_major> af[2];
        wmma::fragment<wmma::matrix_b, 16, 16, 8, wmma::precision::tf32,
                       wmma::row_major> bf[2];
#pragma unroll
        for (int mi = 0; mi < 2; ++mi) {
            wmma::load_matrix_sync(af[mi],
                &g_lrotP[(size_t)(m0 + mi * 16) * KP + k], KP);
#pragma unroll
            for (int e = 0; e < af[mi].num_elements; ++e)
                af[mi].x[e] = wmma::__float_to_tf32(af[mi].x[e]);
        }
#pragma unroll
        for (int ni = 0; ni < 2; ++ni) {
            wmma::load_matrix_sync(bf[ni],
                &g_pdG[(size_t)k * NSTR + n0 + ni * 16], NSTR);
#pragma unroll
            for (int e = 0; e < bf[ni].num_elements; ++e)
                bf[ni].x[e] = wmma::__float_to_tf32(bf[ni].x[e]);
        }
#pragma unroll
        for (int mi = 0; mi < 2; ++mi)
#pragma unroll
            for (int ni = 0; ni < 2; ++ni)
                wmma::mma_sync(acc[mi][ni], af[mi], bf[ni], acc[mi][ni]);
    }
#pragma unroll
    for (int mi = 0; mi < 2; ++mi)
#pragma unroll
        for (int ni = 0; ni < 2; ++ni)
            wmma::store_matrix_sync(
                &g_vp[(size_t)(m0 + mi * 16) * NSTR + n0 + ni * 16],
                acc[mi][ni], NSTR, wmma::mem_row_major);
}

// ---------------------------------------------------------------------------
// Kernel C2: shape blend + staged pose term + LBS + translation.
// ---------------------------------------------------------------------------
__global__ __launch_bounds__(CBLK) void kC2(const float* __restrict__ betas,
                                            const float* __restrict__ trans,
                                            float* __restrict__ out, int Btot) {
    __shared__ __align__(16) float2 G2[TBH][NJ][12];
    __shared__ __align__(16) float bet_sh[NB][TB];
    __shared__ __align__(16) float2 tr2[TBH][3];

    int b0 = blockIdx.y * TB;
    int bcnt = Btot - b0; if (bcnt > TB) bcnt = TB;
    int tid = threadIdx.x;

    for (int i = tid; i < TBH * NJ * 12; i += CBLK) {
        int q = i / (NJ * 12), k = i % (NJ * 12);
        int be = 2 * q, bo = 2 * q + 1;
        float ge = (be < bcnt) ? g_G[(size_t)(b0 + be) * NJ * 12 + k] : 0.f;
        float go = (bo < bcnt) ? g_G[(size_t)(b0 + bo) * NJ * 12 + k] : 0.f;
        G2[q][k / 12][k % 12] = make_float2(ge, go);
    }
    for (int i = tid; i < NB * TB; i += CBLK) {
        int s = i / TB, bb = i % TB;
        bet_sh[s][bb] = (bb < bcnt) ? betas[(b0 + bb) * NB + s] : 0.f;
    }
    for (int i = tid; i < TBH * 3; i += CBLK) {
        int q = i / 3, c = i % 3;
        int be = 2 * q, bo = 2 * q + 1;
        float te = (be < bcnt) ? trans[(b0 + be) * 3 + c] : 0.f;
        float to = (bo < bcnt) ? trans[(b0 + bo) * 3 + c] : 0.f;
        tr2[q][c] = make_float2(te, to);
    }
    __syncthreads();

    int v = blockIdx.x * CBLK + tid;
    int vc = v < NVERT ? v : NVERT - 1;
    bool valid = v < NVERT;

    u64 A0[TBH], A1[TBH], A2[TBH];
    {
        u64 t0 = pack2(__ldg(&g_vtT[0 * NVERT + vc]));
        u64 t1 = pack2(__ldg(&g_vtT[1 * NVERT + vc]));
        u64 t2 = pack2(__ldg(&g_vtT[2 * NVERT + vc]));
#pragma unroll
        for (int q = 0; q < TBH; ++q) { A0[q] = t0; A1[q] = t1; A2[q] = t2; }
    }

    // Shape blend (fp32 precision)
#pragma unroll
    for (int s = 0; s < NB; ++s) {
        u64 sa = pack2(__ldg(&g_sdT[(size_t)(0 * NB + s) * NVERT + vc]));
        u64 sb = pack2(__ldg(&g_sdT[(size_t)(1 * NB + s) * NVERT + vc]));
        u64 sc = pack2(__ldg(&g_sdT[(size_t)(2 * NB + s) * NVERT + vc]));
        const ulonglong2* l = reinterpret_cast<const ulonglong2*>(bet_sh[s]);
#pragma unroll
        for (int h = 0; h < TBH / 2; ++h) {
            ulonglong2 lv = l[h];
            A0[2*h]   = fma2(sa, lv.x, A0[2*h]);
            A0[2*h+1] = fma2(sa, lv.y, A0[2*h+1]);
            A1[2*h]   = fma2(sb, lv.x, A1[2*h]);
            A1[2*h+1] = fma2(sb, lv.y, A1[2*h+1]);
            A2[2*h]   = fma2(sc, lv.x, A2[2*h]);
            A2[2*h+1] = fma2(sc, lv.y, A2[2*h+1]);
        }
    }

    // Add pose blend from GEMM scratch (coalesced over v)
#pragma unroll
    for (int q = 0; q < TBH; ++q) {
        int be = b0 + 2 * q; if (be > Btot - 1) be = Btot - 1;
        int bo = b0 + 2 * q + 1; if (bo > Btot - 1) bo = Btot - 1;
        const float* re = g_vp + (size_t)be * NSTR + vc;
        const float* ro = g_vp + (size_t)bo * NSTR + vc;
        A0[q] = add2(A0[q], pack_pair(__ldg(re), __ldg(ro)));
        A1[q] = add2(A1[q], pack_pair(__ldg(re + NVC), __ldg(ro + NVC)));
        A2[q] = add2(A2[q], pack_pair(__ldg(re + 2 * NVC), __ldg(ro + 2 * NVC)));
    }

    // Weights
    float wv[NJ];
#pragma unroll
    for (int j = 0; j < NJ; ++j) wv[j] = __ldg(&g_wT[(size_t)j * NVERT + vc]);

    // LBS: T = sum_j w_j G_j, then apply
#pragma unroll
    for (int q = 0; q < TBH; ++q) {
        u64 T[12];
#pragma unroll
        for (int k = 0; k < 12; ++k) T[k] = 0ull;
        const ulonglong2* gq = reinterpret_cast<const ulonglong2*>(G2[q][0]);
#pragma unroll 4
        for (int j = 0; j < NJ; ++j) {
            u64 wj = pack2(wv[j]);
            const ulonglong2* g = gq + j * 6;
#pragma unroll
            for (int k = 0; k < 6; ++k) {
                ulonglong2 gg = g[k];
                T[2*k]   = fma2(wj, gg.x, T[2*k]);
                T[2*k+1] = fma2(wj, gg.y, T[2*k+1]);
            }
        }
        u64 ox = fma2(T[0], A0[q], fma2(T[1], A1[q], fma2(T[2], A2[q], T[3])));
        u64 oy = fma2(T[4], A0[q], fma2(T[5], A1[q], fma2(T[6], A2[q], T[7])));
        u64 oz = fma2(T[8], A0[q], fma2(T[9], A1[q], fma2(T[10], A2[q], T[11])));
        const u64* tq = reinterpret_cast<const u64*>(tr2[q]);
        ox = add2(ox, tq[0]);
        oy = add2(oy, tq[1]);
        oz = add2(oz, tq[2]);
        float xe, xo, ye, yo, ze, zo;
        unpack2(ox, xe, xo);
        unpack2(oy, ye, yo);
        unpack2(oz, ze, zo);
        int be = 2 * q, bo = 2 * q + 1;
        if (valid && be < bcnt) {
            size_t o = ((size_t)(b0 + be) * NVERT + v) * 3;
            out[o + 0] = xe; out[o + 1] = ye; out[o + 2] = ze;
        }
        if (valid && bo < bcnt) {
            size_t o = ((size_t)(b0 + bo) * NVERT + v) * 3;
            out[o + 0] = xo; out[o + 1] = yo; out[o + 2] = zo;
        }
    }
}

// ---------------------------------------------------------------------------
// Kernel D: joints = J_regressor @ result, grid (B, VSPL), atomic finish.
// ---------------------------------------------------------------------------
__global__ __launch_bounds__(256) void kD(const float* __restrict__ Jr,
                                          const float* __restrict__ result,
                                          float* __restrict__ joints) {
    int b = blockIdx.x;
    int sp = blockIdx.y;
    int v0 = sp * VCH;
    int v1 = v0 + VCH; if (v1 > NVERT) v1 = NVERT;

    float acc[NJ][3];
#pragma unroll
    for (int j = 0; j < NJ; ++j) { acc[j][0] = 0.f; acc[j][1] = 0.f; acc[j][2] = 0.f; }

    const float* rb = result + (size_t)b * NVERT * 3;
    for (int v = v0 + threadIdx.x; v < v1; v += 256) {
        float rx = rb[v * 3 + 0], ry = rb[v * 3 + 1], rz = rb[v * 3 + 2];
#pragma unroll
        for (int j = 0; j < NJ; ++j) {
            float w = __ldg(&Jr[j * NVERT + v]);
            acc[j][0] = fmaf(w, rx, acc[j][0]);
            acc[j][1] = fmaf(w, ry, acc[j][1]);
            acc[j][2] = fmaf(w, rz, acc[j][2]);
        }
    }
    __shared__ float sm[NJ * 3];
    if (threadIdx.x < NJ * 3) sm[threadIdx.x] = 0.f;
    __syncthreads();
#pragma unroll
    for (int j = 0; j < NJ; ++j) {
#pragma unroll
        for (int c = 0; c < 3; ++c) {
            float x = acc[j][c];
#pragma unroll
            for (int off = 16; off > 0; off >>= 1)
                x += __shfl_xor_sync(0xffffffffu, x, off);
            if ((threadIdx.x & 31) == 0) atomicAdd(&sm[j * 3 + c], x);
        }
    }
    __syncthreads();
    if (threadIdx.x < NJ * 3)
        atomicAdd(&joints[(size_t)b * NJ * 3 + threadIdx.x], sm[threadIdx.x]);
}

// ---------------------------------------------------------------------------
extern "C" void kernel_launch(void* const* d_in, const int* in_sizes, int n_in,
                              void* d_out, int out_size) {
    const float* betas  = (const float*)d_in[0];
    const float* thetas = (const float*)d_in[1];
    const float* trans  = (const float*)d_in[2];
    const float* scale  = (const float*)d_in[3];
    const float* vt     = (const float*)d_in[4];
    const float* sd     = (const float*)d_in[5];
    const float* pd     = (const float*)d_in[6];
    const float* Jr     = (const float*)d_in[7];
    const float* wgt    = (const float*)d_in[8];

    int Btot = in_sizes[0] / NB;
    float* out = (float*)d_out;
    float* joints = out + (size_t)Btot * NVERT * 3;

    dim3 tb(32, 8);
    dim3 gpd((KP + 31) / 32, NVC / 32, 3);
    kTpdG<<<gpd, tb>>>(pd);
    dim3 g3((NVERT + 31) / 32, 1, 3);
    kT3<<<g3, tb>>>(wgt, sd, vt);

    kA<<<NJ, 256>>>(Jr);
    kB<<<Btot, 32>>>(betas, thetas, scale, joints);

    dim3 gg(NSTR / BN, (Btot + BM - 1) / BM);
    kG<<<gg, 256>>>();

    dim3 gc((NVERT + CBLK - 1) / CBLK, (Btot + TB - 1) / TB);
    kC2<<<gc, CBLK>>>(betas, trans, out, Btot);

    dim3 gd(Btot, VSPL);
    kD<<<gd, 256>>>(Jr, out, joints);
}